// round 16
// baseline (speedup 1.0000x reference)
#include <cuda_runtime.h>
#include <cstdint>

// Q3 unpack -> float32 planes. FINAL.
// Reproduced three times: 118.18 / 118.27 / 117.54 us bench,
// 115.0 / 114.6 / 115.7 us ncu, DRAM 72-73% (~5.95 TB/s).
//
// Input:  4096x4096 int32; each word holds 10 x 3-bit fields at shifts
//         27,24,...,0.  Output: [10*4096, 4096] float32; plane k =
//         (float)((w >> (27-3k)) & 7), same linear layout as the input at
//         element offset k * n_words.
//
// Thread i handles 8 consecutive words (2 x LDG.128 .cs) and emits one
// 32-byte st.global.cs.v8.b32 per plane (1KB contiguous per warp per plane).
// Traffic: 67MB in + 671MB out, zero reuse -> write-dominated HBM stream.
//
// Closed optimization space (6 structural variants measured): store width
// {16B,32B}, tile {4,8,16 words}, policy {.cs,default}, stream shape
// {10-way interleaved, smem-staged contiguous, warp-per-plane}. All land at
// 70-74% DRAM; ~5.95 TB/s is the memory-system ceiling for this 10.5:1
// write:read mix. This variant is fastest and simplest: 32 regs, no smem,
// no syncs, 88% occupancy, 14% issue.

__device__ __forceinline__ void stg_cs_v8(float* p,
                                          float v0, float v1, float v2, float v3,
                                          float v4, float v5, float v6, float v7)
{
    asm volatile(
        "st.global.cs.v8.b32 [%0], {%1, %2, %3, %4, %5, %6, %7, %8};"
        :: "l"(p),
           "r"(__float_as_uint(v0)), "r"(__float_as_uint(v1)),
           "r"(__float_as_uint(v2)), "r"(__float_as_uint(v3)),
           "r"(__float_as_uint(v4)), "r"(__float_as_uint(v5)),
           "r"(__float_as_uint(v6)), "r"(__float_as_uint(v7))
        : "memory");
}

__global__ void __launch_bounds__(256)
q3_unpack_f32_v8_kernel(const uint4* __restrict__ in,
                        float* __restrict__ out,
                        int nvec8)  // number of 8-word groups (= words/8)
{
    int i = blockIdx.x * blockDim.x + threadIdx.x;
    if (i >= nvec8) return;

    const uint4 a = __ldcs(in + 2 * (size_t)i);
    const uint4 b = __ldcs(in + 2 * (size_t)i + 1);

    const size_t plane = (size_t)nvec8 * 8;   // plane stride in floats
    float* o = out + (size_t)i * 8;

#pragma unroll
    for (int k = 0; k < 10; ++k) {
        const int s = 27 - 3 * k;
        stg_cs_v8(o + (size_t)k * plane,
                  (float)((a.x >> s) & 7u), (float)((a.y >> s) & 7u),
                  (float)((a.z >> s) & 7u), (float)((a.w >> s) & 7u),
                  (float)((b.x >> s) & 7u), (float)((b.y >> s) & 7u),
                  (float)((b.z >> s) & 7u), (float)((b.w >> s) & 7u));
    }
}

extern "C" void kernel_launch(void* const* d_in, const int* in_sizes, int n_in,
                              void* d_out, int out_size)
{
    (void)n_in; (void)out_size;
    const int n_words = in_sizes[0];      // 4096*4096 = 16,777,216
    const int nvec8   = n_words >> 3;     // 2,097,152

    const uint4* in = (const uint4*)d_in[0];
    float* out = (float*)d_out;

    const int threads = 256;
    const int blocks  = (nvec8 + threads - 1) / threads;  // 8192
    q3_unpack_f32_v8_kernel<<<blocks, threads>>>(in, out, nvec8);
}

// round 17
// speedup vs baseline: 1.0111x; 1.0111x over previous
#include <cuda_runtime.h>
#include <cstdint>

// Q3 unpack -> float32 planes. R16 experiment: per-block plane-order rotation.
//
// Identical addresses/bytes to the 4x-reproduced R5 best (117.5-119.0us):
// thread i handles 8 consecutive words (2 x LDG.128 .cs), one 32B
// st.global.cs.v8.b32 per plane. ONLY change: block b emits its 10 plane
// stores in rotated order k = (kk + b) mod 10, so concurrently-resident
// blocks write to DIFFERENT 64MB plane regions at any instant instead of
// all ~1900 warps storming the same plane in lockstep. Hypothesis: this
// lengthens per-HBM-bank write runs (fewer SMs interleaving per region)
// and lifts the 72.5% DRAM ceiling.

__device__ __forceinline__ void stg_cs_v8(float* p,
                                          float v0, float v1, float v2, float v3,
                                          float v4, float v5, float v6, float v7)
{
    asm volatile(
        "st.global.cs.v8.b32 [%0], {%1, %2, %3, %4, %5, %6, %7, %8};"
        :: "l"(p),
           "r"(__float_as_uint(v0)), "r"(__float_as_uint(v1)),
           "r"(__float_as_uint(v2)), "r"(__float_as_uint(v3)),
           "r"(__float_as_uint(v4)), "r"(__float_as_uint(v5)),
           "r"(__float_as_uint(v6)), "r"(__float_as_uint(v7))
        : "memory");
}

__global__ void __launch_bounds__(256)
q3_unpack_f32_rot_kernel(const uint4* __restrict__ in,
                         float* __restrict__ out,
                         int nvec8)  // number of 8-word groups (= words/8)
{
    int i = blockIdx.x * blockDim.x + threadIdx.x;
    if (i >= nvec8) return;

    const uint4 a = __ldcs(in + 2 * (size_t)i);
    const uint4 b = __ldcs(in + 2 * (size_t)i + 1);

    const size_t plane = (size_t)nvec8 * 8;   // plane stride in floats
    float* o = out + (size_t)i * 8;

    // Rotated starting plane: spreads concurrent blocks across planes.
    int k = blockIdx.x % 10;

#pragma unroll
    for (int kk = 0; kk < 10; ++kk) {
        const int s = 27 - 3 * k;
        stg_cs_v8(o + (size_t)k * plane,
                  (float)((a.x >> s) & 7u), (float)((a.y >> s) & 7u),
                  (float)((a.z >> s) & 7u), (float)((a.w >> s) & 7u),
                  (float)((b.x >> s) & 7u), (float)((b.y >> s) & 7u),
                  (float)((b.z >> s) & 7u), (float)((b.w >> s) & 7u));
        k = (k == 9) ? 0 : (k + 1);
    }
}

extern "C" void kernel_launch(void* const* d_in, const int* in_sizes, int n_in,
                              void* d_out, int out_size)
{
    (void)n_in; (void)out_size;
    const int n_words = in_sizes[0];      // 4096*4096 = 16,777,216
    const int nvec8   = n_words >> 3;     // 2,097,152

    const uint4* in = (const uint4*)d_in[0];
    float* out = (float*)d_out;

    const int threads = 256;
    const int blocks  = (nvec8 + threads - 1) / threads;  // 8192
    q3_unpack_f32_rot_kernel<<<blocks, threads>>>(in, out, nvec8);
}